// round 12
// baseline (speedup 1.0000x reference)
#include <cuda_runtime.h>
#include <cstdint>

#define M_ATOMS 9216
#define A_ATOM  36
#define K_NB    24
#define D0      64
#define KC      3
#define HEADS   4
#define DHD     16
#define RBF_N   16
#define MAXB    4
#define KIN_DIM 99
#define OUTC    144   /* 64 (k) + 64 (v0) + 16 (v1) */
#define BIGF    1e9f
#define EPSF    1e-5f
#define FULLW   0xffffffffu
#define KNN_WCAP 192
#define KNN_TOT  512
#define PQ_BLOCKS 1152
#define CBLK     36            /* compact blocks, 256 atoms each */
#define PREP_TOT (KIN_DIM * OUTC + 21 * OUTC + OUTC)   /* 17424 */
#define PREP_BLK ((PREP_TOT + 255) / 256)              /* 69 */

// ---------------- device scratch ----------------
__device__ int           g_nM;
__device__ int           g_midx[M_ATOMS];
__device__ float4        g_cxyz[M_ATOMS];
__device__ int           g_knn[M_ATOMS * K_NB];
__device__ unsigned char g_maskf[M_ATOMS];
__device__ int           g_bcnt[CBLK];
__device__ float         g_WT[KIN_DIM * OUTC];     // [kk][144]
__device__ float         g_W2[21 * OUTC];          // We @ W_edge
__device__ float         g_b2[OUTC];
__device__ float         g_P[M_ATOMS * OUTC];
__device__ float         g_Qv[M_ATOMS * 64];
__device__ float         g_S[M_ATOMS * 64];

__device__ __forceinline__ float wedge_elem(int c, int d,
                                            const float* Wk, const float* Wv0,
                                            const float* Wv1) {
    int kk = 64 + c;
    if (d < 64)  return Wk [kk * 64 + d];
    if (d < 128) return Wv0[kk * 64 + (d - 64)];
    return Wv1[kk * 16 + (d - 128)];
}

// ---------------- L1a: blocks [0,36) mask+count, blocks [36,105) weight prep ----------------
__global__ void __launch_bounds__(256) mask_prep_kernel(
    const int* __restrict__ seq, const void* __restrict__ aamask,
    const float* __restrict__ Wk, const float* __restrict__ Wv0,
    const float* __restrict__ Wv1, const float* __restrict__ We,
    const float* __restrict__ be) {
    int tid = threadIdx.x;
    if (blockIdx.x >= CBLK) {
        int idx = (blockIdx.x - CBLK) * 256 + tid;
        const int N_WT = KIN_DIM * OUTC;
        const int N_W2 = 21 * OUTC;
        if (idx < N_WT) {
            int kk = idx / OUTC, d = idx % OUTC;
            float v;
            if (d < 64)       v = Wk [kk * 64 + d];
            else if (d < 128) v = Wv0[kk * 64 + (d - 64)];
            else              v = Wv1[kk * 16 + (d - 128)];
            g_WT[idx] = v;
        } else if (idx < N_WT + N_W2) {
            int r = idx - N_WT;
            int t = r / OUTC, d = r % OUTC;
            float acc = 0.f;
            for (int c = 0; c < 32; ++c)
                acc = fmaf(We[t * 32 + c], wedge_elem(c, d, Wk, Wv0, Wv1), acc);
            g_W2[r] = acc;
        } else if (idx < N_WT + N_W2 + OUTC) {
            int d = idx - N_WT - N_W2;
            float acc = 0.f;
            for (int c = 0; c < 32; ++c)
                acc = fmaf(be[c], wedge_elem(c, d, Wk, Wv0, Wv1), acc);
            g_b2[d] = acc;
        }
        return;
    }

    // ---- mask role: 256 atoms per block ----
    __shared__ int s_nz_off4, s_f_ok, s_f_one;
    if (tid == 0) { s_nz_off4 = 0; s_f_ok = 1; s_f_one = 0; }
    __syncthreads();
    const unsigned char* am8  = (const unsigned char*)aamask;
    const int*           am32 = (const int*)aamask;
    const float*         amf  = (const float*)aamask;
    const int NA = 21 * A_ATOM;
    for (int p = tid; p < NA; p += 256)
        if ((p & 3) && am8[p]) atomicOr(&s_nz_off4, 1);
    for (int wi = tid; wi < NA / 4; wi += 256) {
        float f = amf[wi];
        if (!(f == 0.0f || f == 1.0f)) atomicAnd(&s_f_ok, 0);
        if (f == 1.0f) atomicOr(&s_f_one, 1);
    }
    __syncthreads();
    int mode = (!s_nz_off4) ? 0 : ((s_f_ok && s_f_one) ? 2 : 1);

    int m = blockIdx.x * 256 + tid;
    int l = m / A_ATOM, a = m % A_ATOM;
    int q = seq[l] * A_ATOM + a;
    int v;
    if (mode == 0)      v = am32[q];
    else if (mode == 1) v = (int)am8[q];
    else                v = (amf[q] != 0.0f);
    int flag = (v != 0);
    g_maskf[m] = (unsigned char)flag;
    int c = __syncthreads_count(flag);
    if (tid == 0) g_bcnt[blockIdx.x] = c;
}

// ---------------- L1b: 36 blocks scatter (block scan + global base) ----------------
__global__ void __launch_bounds__(256) scatter_kernel(const float* __restrict__ xyz) {
    __shared__ int s_cnt[CBLK];
    __shared__ int s_ws[8];
    int tid = threadIdx.x, lane = tid & 31, wid = tid >> 5;
    if (tid < CBLK) s_cnt[tid] = g_bcnt[tid];
    __syncthreads();
    int base = 0, total = 0;
#pragma unroll
    for (int i = 0; i < CBLK; ++i) {
        if (i < (int)blockIdx.x) base += s_cnt[i];
        total += s_cnt[i];
    }
    if (blockIdx.x == 0 && tid == 0) g_nM = total;

    int m = blockIdx.x * 256 + tid;
    int flag = g_maskf[m];
    int v = flag;
#pragma unroll
    for (int off = 1; off < 32; off <<= 1) {
        int o = __shfl_up_sync(FULLW, v, off);
        if (lane >= off) v += o;
    }
    if (lane == 31) s_ws[wid] = v;
    __syncthreads();
    if (wid == 0 && lane < 8) {
        int t = s_ws[lane];
#pragma unroll
        for (int off = 1; off < 8; off <<= 1) {
            int o = __shfl_up_sync(0xffu, t, off);
            if (lane >= off) t += o;
        }
        s_ws[lane] = t;
    }
    __syncthreads();
    if (flag) {
        int pos = base + (wid ? s_ws[wid - 1] : 0) + v - 1;
        g_midx[pos] = m;
        g_cxyz[pos] = make_float4(xyz[m * 3], xyz[m * 3 + 1], xyz[m * 3 + 2],
                                  __int_as_float(m));
    }
}

// ---------------- L2: blocks [0,9216) = knn, blocks [9216,+1152) = pq ----------------
__device__ __forceinline__ unsigned long long knn_pack(float d, int j) {
    return ((unsigned long long)__float_as_uint(d) << 32) | (unsigned)j;
}

__global__ void __launch_bounds__(288) knnpq_kernel(
    const float* __restrict__ state, const float* __restrict__ grads,
    const float* __restrict__ Wq, const float* __restrict__ Wself,
    const float* __restrict__ b0, const float* __restrict__ xyz,
    float* __restrict__ out) {
    __shared__ __align__(16) float s_stT[64][8];
    __shared__ unsigned long long s_key[8][KNN_WCAP];
    __shared__ int   s_cnt[8];
    __shared__ float s_samp[128];
    __shared__ float s_T;
    __shared__ float s_nr[8][3];
    __shared__ int   s_m[8];

    int nM = g_nM;
    int tid = threadIdx.x, w = tid >> 5, lane = tid & 31;

    if (blockIdx.x >= M_ATOMS) {
        // ================= pq role =================
        int pbid = blockIdx.x - M_ATOMS;
        {
            const int total = M_ATOMS * 3 + M_ATOMS * D0;
            for (int i = pbid * 288 + tid; i < total; i += PQ_BLOCKS * 288)
                out[i] = (i < M_ATOMS * 3) ? xyz[i] : state[i - M_ATOMS * 3];
        }
        int base = pbid * 8;
        if (base >= nM) return;
        int nhere = min(8, nM - base);

        if (tid < 8) s_m[tid] = g_midx[base + ((tid < nhere) ? tid : 0)];
        __syncthreads();
        for (int i = tid; i < 8 * 64; i += 288) {
            int a = i >> 6, k = i & 63;
            s_stT[k][a] = state[s_m[a] * 64 + k];
        }
        if (tid >= 264) {
            int t = tid - 264;
            int a = t / 3, c = t % 3;
            int m = s_m[a];
            float s = EPSF;
#pragma unroll
            for (int dd = 0; dd < 3; ++dd) {
                float v = grads[(c * M_ATOMS + m) * 3 + dd];
                s = fmaf(v, v, s);
            }
            s_nr[a][c] = sqrtf(s);
        }
        __syncthreads();

        if (tid < OUTC) {
            float acc[8];
#pragma unroll
            for (int a = 0; a < 8; ++a) acc[a] = 0.f;
#pragma unroll 8
            for (int k = 0; k < 64; ++k) {
                float wv = g_WT[k * OUTC + tid];
                float4 s0 = *(const float4*)&s_stT[k][0];
                float4 s1 = *(const float4*)&s_stT[k][4];
                acc[0] = fmaf(s0.x, wv, acc[0]);
                acc[1] = fmaf(s0.y, wv, acc[1]);
                acc[2] = fmaf(s0.z, wv, acc[2]);
                acc[3] = fmaf(s0.w, wv, acc[3]);
                acc[4] = fmaf(s1.x, wv, acc[4]);
                acc[5] = fmaf(s1.y, wv, acc[5]);
                acc[6] = fmaf(s1.z, wv, acc[6]);
                acc[7] = fmaf(s1.w, wv, acc[7]);
            }
            for (int a = 0; a < nhere; ++a)
                g_P[s_m[a] * OUTC + tid] = acc[a];
        } else if (tid < OUTC + 128) {
            int t = tid - OUTC;
            int d = t & 63;
            bool isq = (t < 64);
            const float* W = isq ? Wq : Wself;
            float acc[8];
            float init = isq ? 0.f : b0[d];
#pragma unroll
            for (int a = 0; a < 8; ++a) acc[a] = init;
#pragma unroll 8
            for (int k = 0; k < 64; ++k) {
                float wv = W[k * 64 + d];
                float4 s0 = *(const float4*)&s_stT[k][0];
                float4 s1 = *(const float4*)&s_stT[k][4];
                acc[0] = fmaf(s0.x, wv, acc[0]);
                acc[1] = fmaf(s0.y, wv, acc[1]);
                acc[2] = fmaf(s0.z, wv, acc[2]);
                acc[3] = fmaf(s0.w, wv, acc[3]);
                acc[4] = fmaf(s1.x, wv, acc[4]);
                acc[5] = fmaf(s1.y, wv, acc[5]);
                acc[6] = fmaf(s1.z, wv, acc[6]);
                acc[7] = fmaf(s1.w, wv, acc[7]);
            }
            if (isq) {
#pragma unroll
                for (int c = 0; c < KC; ++c) {
                    float wv = Wq[(64 + c) * 64 + d];
                    for (int a = 0; a < 8; ++a)
                        acc[a] = fmaf(s_nr[a][c], wv, acc[a]);
                }
                for (int a = 0; a < nhere; ++a)
                    g_Qv[s_m[a] * 64 + d] = acc[a];
            } else {
                for (int a = 0; a < nhere; ++a)
                    g_S[s_m[a] * 64 + d] = acc[a];
            }
        }
        return;
    }

    // ================= knn role =================
    int qi = blockIdx.x;
    if (qi >= nM) return;
    unsigned lmask = (1u << lane) - 1u;
    int m = g_midx[qi];
    float4 me = g_cxyz[qi];
    int target = min(K_NB, nM - 1);

    if (tid < K_NB) g_knn[m * K_NB + tid] = m;   // default fill

    if (tid < 128) {
        int j = (int)(((long long)tid * nM) >> 7);
        float d2 = BIGF;
        if (j != qi) {
            float4 c = g_cxyz[j];
            float dx = c.x - me.x, dy = c.y - me.y, dz = c.z - me.z;
            d2 = dx * dx + dy * dy + dz * dz;
        }
        s_samp[tid] = d2;
    }
    __syncthreads();
    if (tid < 32) {
        float a0 = s_samp[lane], a1 = s_samp[32 + lane];
        float a2 = s_samp[64 + lane], a3 = s_samp[96 + lane];
        float m3 = BIGF;
        for (int r = 0; r < 3; ++r) {
            float v = fminf(fminf(a0, a1), fminf(a2, a3));
#pragma unroll
            for (int off = 16; off; off >>= 1)
                v = fminf(v, __shfl_xor_sync(FULLW, v, off));
            m3 = v;
            if (a0 == v) a0 = BIGF;
            else if (a1 == v) a1 = BIGF;
            else if (a2 == v) a2 = BIGF;
            else if (a3 == v) a3 = BIGF;
        }
        if (lane == 0) s_T = fminf(m3, BIGF * 0.4f);
    }
    __syncthreads();
    float T = s_T;

    int seg0 = 0, seg1 = 0;
    if (w < 8) {
        seg0 = (int)(((long long)w * nM) >> 3);
        seg1 = (int)(((long long)(w + 1) * nM) >> 3);
    }
    bool valid = false;
    int totc = 0;
    for (int attempt = 0; attempt < 12; ++attempt) {
        if (w < 8) {
            int cnt = 0;
            for (int j0 = seg0; j0 < seg1; j0 += 128) {
                float d2[4];
#pragma unroll
                for (int u = 0; u < 4; ++u) {
                    int j = j0 + u * 32 + lane;
                    float dd = BIGF;
                    if (j < seg1 && j != qi) {
                        float4 c = g_cxyz[j];
                        float dx = c.x - me.x, dy = c.y - me.y, dz = c.z - me.z;
                        dd = dx * dx + dy * dy + dz * dz;
                    }
                    d2[u] = dd;
                }
#pragma unroll
                for (int u = 0; u < 4; ++u) {
                    bool p = (d2[u] <= T);
                    unsigned ball = __ballot_sync(FULLW, p);
                    if (p) {
                        int pos = cnt + __popc(ball & lmask);
                        if (pos < KNN_WCAP)
                            s_key[w][pos] = knn_pack(d2[u], j0 + u * 32 + lane);
                    }
                    cnt += __popc(ball);
                }
            }
            if (lane == 0) s_cnt[w] = cnt;
        }
        __syncthreads();
        totc = 0;
        bool over = false;
#pragma unroll
        for (int i = 0; i < 8; ++i) {
            int ci = s_cnt[i];
            totc += ci;
            over |= (ci > KNN_WCAP);
        }
        over |= (totc > KNN_TOT);
        if (totc >= target && !over) { valid = true; break; }
        if (totc < target) T = fminf(T * 4.0f, BIGF * 0.4f);
        else               T = T * 0.35f;
        __syncthreads();
    }

    if (valid) {
        int pre[8];
        {
            int acc = 0;
#pragma unroll
            for (int i = 0; i < 8; ++i) { pre[i] = acc; acc += s_cnt[i]; }
        }
        if (totc <= 288) {
            if (tid < totc) {
                int sg = 0;
#pragma unroll
                for (int i = 1; i < 8; ++i) if (tid >= pre[i]) sg = i;
                unsigned long long mine = s_key[sg][tid - pre[sg]];
                int rk = 0;
#pragma unroll
                for (int w2 = 0; w2 < 8; ++w2) {
                    int c2 = s_cnt[w2];
                    for (int j = 0; j < c2; ++j)
                        rk += (s_key[w2][j] < mine) ? 1 : 0;
                }
                if (rk < target)
                    g_knn[m * K_NB + rk] = g_midx[(unsigned)(mine & 0xffffffffu)];
            }
        } else {
            unsigned long long mine[2];
            int rk[2];
#pragma unroll
            for (int o = 0; o < 2; ++o) {
                int g = tid + o * 288;
                unsigned long long k = ~0ull;
                if (g < totc) {
                    int sg = 0;
#pragma unroll
                    for (int i = 1; i < 8; ++i) if (g >= pre[i]) sg = i;
                    k = s_key[sg][g - pre[sg]];
                }
                mine[o] = k;
                rk[o] = 0;
            }
#pragma unroll
            for (int w2 = 0; w2 < 8; ++w2) {
                int c2 = s_cnt[w2];
                for (int j = 0; j < c2; ++j) {
                    unsigned long long kj = s_key[w2][j];
#pragma unroll
                    for (int o = 0; o < 2; ++o) rk[o] += (kj < mine[o]) ? 1 : 0;
                }
            }
#pragma unroll
            for (int o = 0; o < 2; ++o) {
                if (mine[o] != ~0ull && rk[o] < target)
                    g_knn[m * K_NB + rk[o]] = g_midx[(unsigned)(mine[o] & 0xffffffffu)];
            }
        }
    } else if (w == 0) {
        unsigned long long last = 0ull;
        for (int r = 0; r < K_NB; ++r) {
            unsigned long long best = ~0ull;
            for (int j = lane; j < nM; j += 32) {
                float d2 = BIGF;
                if (j != qi) {
                    float4 c = g_cxyz[j];
                    float dx = c.x - me.x, dy = c.y - me.y, dz = c.z - me.z;
                    d2 = dx * dx + dy * dy + dz * dz;
                }
                unsigned long long p = knn_pack(d2, j);
                if (p >= last && p < best) best = p;
            }
#pragma unroll
            for (int off = 16; off; off >>= 1) {
                unsigned long long o = __shfl_xor_sync(FULLW, best, off);
                if (o < best) best = o;
            }
            if (lane == r) {
                float d = __uint_as_float((unsigned)(best >> 32));
                if (best != ~0ull && d < BIGF * 0.5f)
                    g_knn[m * K_NB + r] = g_midx[(unsigned)best & 0xffffffffu];
            }
            last = best + 1ull;
        }
    }
}

// ---------------- L3: per-atom edge attention, 288 threads, edge-split kv ----------------
__global__ void __launch_bounds__(288) attn_kernel(
    const int* __restrict__ seq, const float* __restrict__ xyz,
    const int* __restrict__ num_bonds, const float* __restrict__ grads,
    const float* __restrict__ Wo0, float* __restrict__ out) {
    if (blockIdx.x >= g_nM) return;
    int m = g_midx[blockIdx.x];
    int tid = threadIdx.x;
    int lane = tid & 31;

    __shared__ float s_kv[K_NB][OUTC + 1];
    __shared__ float s_q[64];
    __shared__ float s_rbf[K_NB][RBF_N];
    __shared__ float s_dirv[K_NB][3];
    __shared__ float s_l1j[K_NB][KC][3];
    __shared__ float s_inv[K_NB][KC];
    __shared__ int   s_bond[K_NB];
    __shared__ float s_attn[HEADS][K_NB];
    __shared__ float s_o0[64];
    __shared__ float s_coef[K_NB][4];
    __shared__ int   s_idx[K_NB];
    __shared__ float s_ok[K_NB];

    // ---- phase 0: q load + per-edge geometry ----
    if (tid < 64) {
        s_q[tid] = g_Qv[m * 64 + tid];
    } else if (tid < 64 + K_NB) {
        int e = tid - 64;
        int j = g_knn[m * K_NB + e];
        s_idx[e] = j;
        float rx = xyz[j * 3]     - xyz[m * 3];
        float ry = xyz[j * 3 + 1] - xyz[m * 3 + 1];
        float rz = xyz[j * 3 + 2] - xyz[m * 3 + 2];
        float d2 = rx * rx + ry * ry + rz * rz;
        float dist = sqrtf(d2 + EPSF);
        float inv_d = 1.f / dist;
        float dvx = rx * inv_d, dvy = ry * inv_d, dvz = rz * inv_d;
        s_dirv[e][0] = dvx; s_dirv[e][1] = dvy; s_dirv[e][2] = dvz;
        s_ok[e] = (j != m) ? 1.f : 0.f;
#pragma unroll
        for (int c = 0; c < KC; ++c) {
            float lx = grads[(c * M_ATOMS + j) * 3 + 0];
            float ly = grads[(c * M_ATOMS + j) * 3 + 1];
            float lz = grads[(c * M_ATOMS + j) * 3 + 2];
            s_l1j[e][c][0] = lx; s_l1j[e][c][1] = ly; s_l1j[e][c][2] = lz;
            s_inv[e][c] = lx * dvx + ly * dvy + lz * dvz;
        }
        int ri = m / A_ATOM, ai = m % A_ATOM;
        int rj = j / A_ATOM, aj = j % A_ATOM;
        int b = 0;
        if (rj == ri) b = num_bonds[(seq[ri] * A_ATOM + ai) * A_ATOM + aj];
        s_bond[e] = min(max(b, 0), MAXB);
#pragma unroll
        for (int t = 0; t < RBF_N; ++t) {
            float r = dist - 0.4f * (float)t;
            s_rbf[e][t] = __expf(-2.f * r * r);
        }
    }
    __syncthreads();

    // ---- phase 1: kv, edge-split — thread (d, half) does 12 edges ----
    {
        int g = (tid >= OUTC) ? 1 : 0;
        int d = tid - g * OUTC;      // 0..143 both halves
        float w2r[RBF_N];
#pragma unroll
        for (int t = 0; t < RBF_N; ++t) w2r[t] = g_W2[t * OUTC + d];
        float wb0 = g_W2[16 * OUTC + d];
        float wb1 = g_W2[17 * OUTC + d];
        float wb2 = g_W2[18 * OUTC + d];
        float wb3 = g_W2[19 * OUTC + d];
        float wb4 = g_W2[20 * OUTC + d];
        float wi0 = g_WT[96 * OUTC + d];
        float wi1 = g_WT[97 * OUTC + d];
        float wi2 = g_WT[98 * OUTC + d];
        float b2  = g_b2[d];
        int e0 = g * 12;
#pragma unroll 4
        for (int ee = 0; ee < 12; ++ee) {
            int e = e0 + ee;
            int j = s_idx[e];
            float acc = b2 + g_P[j * OUTC + d];
#pragma unroll
            for (int t = 0; t < RBF_N; ++t)
                acc = fmaf(s_rbf[e][t], w2r[t], acc);
            int b = s_bond[e];
            float wb = wb0;
            if (b == 1) wb = wb1;
            else if (b == 2) wb = wb2;
            else if (b == 3) wb = wb3;
            else if (b == 4) wb = wb4;
            acc += wb;
            acc = fmaf(s_inv[e][0], wi0, acc);
            acc = fmaf(s_inv[e][1], wi1, acc);
            acc = fmaf(s_inv[e][2], wi2, acc);
            s_kv[e][d] = acc;
        }
    }
    __syncthreads();

    // ---- phase 2: logits + softmax fused (warp h handles head h) ----
    {
        int h = tid >> 5;
        if (h < HEADS) {
            float logit = -1e30f;
            if (lane < K_NB) {
                float acc = 0.f;
#pragma unroll
                for (int dh = 0; dh < DHD; ++dh)
                    acc = fmaf(s_q[h * DHD + dh], s_kv[lane][h * DHD + dh], acc);
                logit = (s_ok[lane] > 0.f) ? acc * 0.25f : -1e9f;
            }
            float mx = logit;
#pragma unroll
            for (int off = 16; off > 0; off >>= 1)
                mx = fmaxf(mx, __shfl_xor_sync(FULLW, mx, off));
            float ex = (lane < K_NB) ? __expf(logit - mx) : 0.f;
            float sm = ex;
#pragma unroll
            for (int off = 16; off > 0; off >>= 1)
                sm += __shfl_xor_sync(FULLW, sm, off);
            if (lane < K_NB) s_attn[h][lane] = ex / sm;
        }
    }
    __syncthreads();

    // ---- phase 3: o0, coef ----
    if (tid < 64) {
        int h = tid >> 4;
        float acc = 0.f;
#pragma unroll
        for (int e = 0; e < K_NB; ++e)
            acc = fmaf(s_attn[h][e], s_kv[e][64 + tid], acc);
        s_o0[tid] = acc;
    } else if (tid < 160) {
        int t = tid - 64;
        int e = t % K_NB, c = t / K_NB;
        float acc = 0.f;
#pragma unroll
        for (int h = 0; h < HEADS; ++h)
            acc = fmaf(s_attn[h][e], s_kv[e][128 + h * 4 + c], acc);
        s_coef[e][c] = acc;
    }
    __syncthreads();

    // ---- phase 4: out0 (state) + out1 via warp-2 shuffle reduction ----
    if (tid < 64) {
        float acc = g_S[m * 64 + tid];
#pragma unroll 8
        for (int i = 0; i < 64; ++i)
            acc = fmaf(s_o0[i], Wo0[i * 64 + tid], acc);
        out[M_ATOMS * 3 + m * 64 + tid] = acc;
    } else if (tid >= 64 && tid < 96) {
        // whole warp 2 participates in the reduction; lanes 24-31 contribute 0
        int e = tid - 64;
        float v0 = 0.f, v1 = 0.f, v2 = 0.f;
        if (e < K_NB) {
            float c0 = s_coef[e][0];
            v0 = c0 * s_dirv[e][0];
            v1 = c0 * s_dirv[e][1];
            v2 = c0 * s_dirv[e][2];
#pragma unroll
            for (int c = 0; c < KC; ++c) {
                float cc = s_coef[e][c + 1];
                v0 = fmaf(cc, s_l1j[e][c][0], v0);
                v1 = fmaf(cc, s_l1j[e][c][1], v1);
                v2 = fmaf(cc, s_l1j[e][c][2], v2);
            }
        }
#pragma unroll
        for (int off = 16; off > 0; off >>= 1) {
            v0 += __shfl_xor_sync(FULLW, v0, off);
            v1 += __shfl_xor_sync(FULLW, v1, off);
            v2 += __shfl_xor_sync(FULLW, v2, off);
        }
        if (e == 0) {
            out[m * 3 + 0] = xyz[m * 3 + 0] + v0 * 0.01f;
            out[m * 3 + 1] = xyz[m * 3 + 1] + v1 * 0.01f;
            out[m * 3 + 2] = xyz[m * 3 + 2] + v2 * 0.01f;
        }
    }
}

// ---------------- launch ----------------
extern "C" void kernel_launch(void* const* d_in, const int* in_sizes, int n_in,
                              void* d_out, int out_size) {
    const int*   seq       = (const int*)d_in[0];
    const float* xyz       = (const float*)d_in[1];
    const void*  aamask    = d_in[2];
    const int*   num_bonds = (const int*)d_in[3];
    const float* state     = (const float*)d_in[4];
    const float* grads     = (const float*)d_in[5];
    int w = 6;
    if (n_in >= 16 && in_sizes[6] == 1) w = 7;
    const float* We    = (const float*)d_in[w + 0];
    const float* be    = (const float*)d_in[w + 1];
    const float* Wq    = (const float*)d_in[w + 2];
    const float* Wk    = (const float*)d_in[w + 3];
    const float* Wv0   = (const float*)d_in[w + 4];
    const float* Wv1   = (const float*)d_in[w + 5];
    const float* Wo0   = (const float*)d_in[w + 6];
    const float* Wself = (const float*)d_in[w + 7];
    const float* b0    = (const float*)d_in[w + 8];
    float* out = (float*)d_out;

    mask_prep_kernel<<<CBLK + PREP_BLK, 256>>>(seq, aamask, Wk, Wv0, Wv1, We, be);
    scatter_kernel<<<CBLK, 256>>>(xyz);
    knnpq_kernel<<<M_ATOMS + PQ_BLOCKS, 288>>>(state, grads, Wq, Wself, b0, xyz, out);
    attn_kernel<<<M_ATOMS, 288>>>(seq, xyz, num_bonds, grads, Wo0, out);
}

// round 13
// speedup vs baseline: 1.0543x; 1.0543x over previous
#include <cuda_runtime.h>
#include <cstdint>

#define M_ATOMS 9216
#define A_ATOM  36
#define K_NB    24
#define D0      64
#define KC      3
#define HEADS   4
#define DHD     16
#define RBF_N   16
#define MAXB    4
#define KIN_DIM 99
#define OUTC    144   /* 64 (k) + 64 (v0) + 16 (v1) */
#define BIGF    1e9f
#define EPSF    1e-5f
#define FULLW   0xffffffffu
#define KNN_WCAP 192
#define KNN_TOT  512
#define PQ_BLOCKS 1152
#define CBLK     36
#define PREP_TOT (KIN_DIM * OUTC + 21 * OUTC + OUTC)
#define PREP_BLK ((PREP_TOT + 255) / 256)

// ---------------- device scratch ----------------
__device__ int           g_nM;
__device__ int           g_midx[M_ATOMS];
__device__ float4        g_cxyz[M_ATOMS];
__device__ int           g_knn[M_ATOMS * K_NB];
__device__ unsigned char g_maskf[M_ATOMS];
__device__ int           g_bcnt[CBLK];
__device__ float         g_WT[KIN_DIM * OUTC];
__device__ float         g_W2[21 * OUTC];
__device__ float         g_b2[OUTC];
__device__ float         g_P[M_ATOMS * OUTC];
__device__ float         g_Qv[M_ATOMS * 64];
__device__ float         g_S[M_ATOMS * 64];

__device__ __forceinline__ float wedge_elem(int c, int d,
                                            const float* Wk, const float* Wv0,
                                            const float* Wv1) {
    int kk = 64 + c;
    if (d < 64)  return Wk [kk * 64 + d];
    if (d < 128) return Wv0[kk * 64 + (d - 64)];
    return Wv1[kk * 16 + (d - 128)];
}

// ---------------- L1a: blocks [0,36) mask+count, rest weight prep ----------------
__global__ void __launch_bounds__(256) mask_prep_kernel(
    const int* __restrict__ seq, const void* __restrict__ aamask,
    const float* __restrict__ Wk, const float* __restrict__ Wv0,
    const float* __restrict__ Wv1, const float* __restrict__ We,
    const float* __restrict__ be) {
    int tid = threadIdx.x;
    if (blockIdx.x >= CBLK) {
        int idx = (blockIdx.x - CBLK) * 256 + tid;
        const int N_WT = KIN_DIM * OUTC;
        const int N_W2 = 21 * OUTC;
        if (idx < N_WT) {
            int kk = idx / OUTC, d = idx % OUTC;
            float v;
            if (d < 64)       v = Wk [kk * 64 + d];
            else if (d < 128) v = Wv0[kk * 64 + (d - 64)];
            else              v = Wv1[kk * 16 + (d - 128)];
            g_WT[idx] = v;
        } else if (idx < N_WT + N_W2) {
            int r = idx - N_WT;
            int t = r / OUTC, d = r % OUTC;
            float acc = 0.f;
            for (int c = 0; c < 32; ++c)
                acc = fmaf(We[t * 32 + c], wedge_elem(c, d, Wk, Wv0, Wv1), acc);
            g_W2[r] = acc;
        } else if (idx < N_WT + N_W2 + OUTC) {
            int d = idx - N_WT - N_W2;
            float acc = 0.f;
            for (int c = 0; c < 32; ++c)
                acc = fmaf(be[c], wedge_elem(c, d, Wk, Wv0, Wv1), acc);
            g_b2[d] = acc;
        }
        return;
    }

    __shared__ int s_nz_off4, s_f_ok, s_f_one;
    if (tid == 0) { s_nz_off4 = 0; s_f_ok = 1; s_f_one = 0; }
    __syncthreads();
    const unsigned char* am8  = (const unsigned char*)aamask;
    const int*           am32 = (const int*)aamask;
    const float*         amf  = (const float*)aamask;
    const int NA = 21 * A_ATOM;
    for (int p = tid; p < NA; p += 256)
        if ((p & 3) && am8[p]) atomicOr(&s_nz_off4, 1);
    for (int wi = tid; wi < NA / 4; wi += 256) {
        float f = amf[wi];
        if (!(f == 0.0f || f == 1.0f)) atomicAnd(&s_f_ok, 0);
        if (f == 1.0f) atomicOr(&s_f_one, 1);
    }
    __syncthreads();
    int mode = (!s_nz_off4) ? 0 : ((s_f_ok && s_f_one) ? 2 : 1);

    int m = blockIdx.x * 256 + tid;
    int l = m / A_ATOM, a = m % A_ATOM;
    int q = seq[l] * A_ATOM + a;
    int v;
    if (mode == 0)      v = am32[q];
    else if (mode == 1) v = (int)am8[q];
    else                v = (amf[q] != 0.0f);
    int flag = (v != 0);
    g_maskf[m] = (unsigned char)flag;
    int c = __syncthreads_count(flag);
    if (tid == 0) g_bcnt[blockIdx.x] = c;
}

// ---------------- L1b: 36 blocks scatter ----------------
__global__ void __launch_bounds__(256) scatter_kernel(const float* __restrict__ xyz) {
    __shared__ int s_cnt[CBLK];
    __shared__ int s_ws[8];
    int tid = threadIdx.x, lane = tid & 31, wid = tid >> 5;
    if (tid < CBLK) s_cnt[tid] = g_bcnt[tid];
    __syncthreads();
    int base = 0, total = 0;
#pragma unroll
    for (int i = 0; i < CBLK; ++i) {
        if (i < (int)blockIdx.x) base += s_cnt[i];
        total += s_cnt[i];
    }
    if (blockIdx.x == 0 && tid == 0) g_nM = total;

    int m = blockIdx.x * 256 + tid;
    int flag = g_maskf[m];
    int v = flag;
#pragma unroll
    for (int off = 1; off < 32; off <<= 1) {
        int o = __shfl_up_sync(FULLW, v, off);
        if (lane >= off) v += o;
    }
    if (lane == 31) s_ws[wid] = v;
    __syncthreads();
    if (wid == 0 && lane < 8) {
        int t = s_ws[lane];
#pragma unroll
        for (int off = 1; off < 8; off <<= 1) {
            int o = __shfl_up_sync(0xffu, t, off);
            if (lane >= off) t += o;
        }
        s_ws[lane] = t;
    }
    __syncthreads();
    if (flag) {
        int pos = base + (wid ? s_ws[wid - 1] : 0) + v - 1;
        g_midx[pos] = m;
        g_cxyz[pos] = make_float4(xyz[m * 3], xyz[m * 3 + 1], xyz[m * 3 + 2],
                                  __int_as_float(m));
    }
}

// ---------------- L2: blocks [0,9216) = knn, blocks [9216,+1152) = pq ----------------
__device__ __forceinline__ unsigned long long knn_pack(float d, int j) {
    return ((unsigned long long)__float_as_uint(d) << 32) | (unsigned)j;
}

__global__ void __launch_bounds__(288) knnpq_kernel(
    const float* __restrict__ state, const float* __restrict__ grads,
    const float* __restrict__ Wq, const float* __restrict__ Wself,
    const float* __restrict__ b0, const float* __restrict__ xyz,
    float* __restrict__ out) {
    __shared__ __align__(16) float s_stT[64][8];
    __shared__ unsigned long long s_key[8][KNN_WCAP];
    __shared__ int   s_cnt[8];
    __shared__ float s_samp[128];
    __shared__ float s_T;
    __shared__ float s_nr[8][3];
    __shared__ int   s_m[8];

    int nM = g_nM;
    int tid = threadIdx.x, w = tid >> 5, lane = tid & 31;

    if (blockIdx.x >= M_ATOMS) {
        // ================= pq role =================
        int pbid = blockIdx.x - M_ATOMS;
        {
            const int total = M_ATOMS * 3 + M_ATOMS * D0;
            for (int i = pbid * 288 + tid; i < total; i += PQ_BLOCKS * 288)
                out[i] = (i < M_ATOMS * 3) ? xyz[i] : state[i - M_ATOMS * 3];
        }
        int base = pbid * 8;
        if (base >= nM) return;
        int nhere = min(8, nM - base);

        if (tid < 8) s_m[tid] = g_midx[base + ((tid < nhere) ? tid : 0)];
        __syncthreads();
        for (int i = tid; i < 8 * 64; i += 288) {
            int a = i >> 6, k = i & 63;
            s_stT[k][a] = state[s_m[a] * 64 + k];
        }
        if (tid >= 264) {
            int t = tid - 264;
            int a = t / 3, c = t % 3;
            int m = s_m[a];
            float s = EPSF;
#pragma unroll
            for (int dd = 0; dd < 3; ++dd) {
                float v = grads[(c * M_ATOMS + m) * 3 + dd];
                s = fmaf(v, v, s);
            }
            s_nr[a][c] = sqrtf(s);
        }
        __syncthreads();

        if (tid < OUTC) {
            float acc[8];
#pragma unroll
            for (int a = 0; a < 8; ++a) acc[a] = 0.f;
#pragma unroll 8
            for (int k = 0; k < 64; ++k) {
                float wv = g_WT[k * OUTC + tid];
                float4 s0 = *(const float4*)&s_stT[k][0];
                float4 s1 = *(const float4*)&s_stT[k][4];
                acc[0] = fmaf(s0.x, wv, acc[0]);
                acc[1] = fmaf(s0.y, wv, acc[1]);
                acc[2] = fmaf(s0.z, wv, acc[2]);
                acc[3] = fmaf(s0.w, wv, acc[3]);
                acc[4] = fmaf(s1.x, wv, acc[4]);
                acc[5] = fmaf(s1.y, wv, acc[5]);
                acc[6] = fmaf(s1.z, wv, acc[6]);
                acc[7] = fmaf(s1.w, wv, acc[7]);
            }
            for (int a = 0; a < nhere; ++a)
                g_P[s_m[a] * OUTC + tid] = acc[a];
        } else if (tid < OUTC + 128) {
            int t = tid - OUTC;
            int d = t & 63;
            bool isq = (t < 64);
            const float* W = isq ? Wq : Wself;
            float acc[8];
            float init = isq ? 0.f : b0[d];
#pragma unroll
            for (int a = 0; a < 8; ++a) acc[a] = init;
#pragma unroll 8
            for (int k = 0; k < 64; ++k) {
                float wv = W[k * 64 + d];
                float4 s0 = *(const float4*)&s_stT[k][0];
                float4 s1 = *(const float4*)&s_stT[k][4];
                acc[0] = fmaf(s0.x, wv, acc[0]);
                acc[1] = fmaf(s0.y, wv, acc[1]);
                acc[2] = fmaf(s0.z, wv, acc[2]);
                acc[3] = fmaf(s0.w, wv, acc[3]);
                acc[4] = fmaf(s1.x, wv, acc[4]);
                acc[5] = fmaf(s1.y, wv, acc[5]);
                acc[6] = fmaf(s1.z, wv, acc[6]);
                acc[7] = fmaf(s1.w, wv, acc[7]);
            }
            if (isq) {
#pragma unroll
                for (int c = 0; c < KC; ++c) {
                    float wv = Wq[(64 + c) * 64 + d];
                    for (int a = 0; a < 8; ++a)
                        acc[a] = fmaf(s_nr[a][c], wv, acc[a]);
                }
                for (int a = 0; a < nhere; ++a)
                    g_Qv[s_m[a] * 64 + d] = acc[a];
            } else {
                for (int a = 0; a < nhere; ++a)
                    g_S[s_m[a] * 64 + d] = acc[a];
            }
        }
        return;
    }

    // ================= knn role =================
    int qi = blockIdx.x;
    if (qi >= nM) return;
    unsigned lmask = (1u << lane) - 1u;
    int m = g_midx[qi];
    float4 me = g_cxyz[qi];
    int target = min(K_NB, nM - 1);

    if (tid < K_NB) g_knn[m * K_NB + tid] = m;

    if (tid < 128) {
        int j = (int)(((long long)tid * nM) >> 7);
        float d2 = BIGF;
        if (j != qi) {
            float4 c = g_cxyz[j];
            float dx = c.x - me.x, dy = c.y - me.y, dz = c.z - me.z;
            d2 = dx * dx + dy * dy + dz * dz;
        }
        s_samp[tid] = d2;
    }
    __syncthreads();
    if (tid < 32) {
        float a0 = s_samp[lane], a1 = s_samp[32 + lane];
        float a2 = s_samp[64 + lane], a3 = s_samp[96 + lane];
        float m3 = BIGF;
        for (int r = 0; r < 3; ++r) {
            float v = fminf(fminf(a0, a1), fminf(a2, a3));
#pragma unroll
            for (int off = 16; off; off >>= 1)
                v = fminf(v, __shfl_xor_sync(FULLW, v, off));
            m3 = v;
            if (a0 == v) a0 = BIGF;
            else if (a1 == v) a1 = BIGF;
            else if (a2 == v) a2 = BIGF;
            else if (a3 == v) a3 = BIGF;
        }
        if (lane == 0) s_T = fminf(m3, BIGF * 0.4f);
    }
    __syncthreads();
    float T = s_T;

    int seg0 = 0, seg1 = 0;
    if (w < 8) {
        seg0 = (int)(((long long)w * nM) >> 3);
        seg1 = (int)(((long long)(w + 1) * nM) >> 3);
    }
    bool valid = false;
    int totc = 0;
    for (int attempt = 0; attempt < 12; ++attempt) {
        if (w < 8) {
            int cnt = 0;
            for (int j0 = seg0; j0 < seg1; j0 += 128) {
                float d2[4];
#pragma unroll
                for (int u = 0; u < 4; ++u) {
                    int j = j0 + u * 32 + lane;
                    float dd = BIGF;
                    if (j < seg1 && j != qi) {
                        float4 c = g_cxyz[j];
                        float dx = c.x - me.x, dy = c.y - me.y, dz = c.z - me.z;
                        dd = dx * dx + dy * dy + dz * dz;
                    }
                    d2[u] = dd;
                }
#pragma unroll
                for (int u = 0; u < 4; ++u) {
                    bool p = (d2[u] <= T);
                    unsigned ball = __ballot_sync(FULLW, p);
                    if (p) {
                        int pos = cnt + __popc(ball & lmask);
                        if (pos < KNN_WCAP)
                            s_key[w][pos] = knn_pack(d2[u], j0 + u * 32 + lane);
                    }
                    cnt += __popc(ball);
                }
            }
            if (lane == 0) s_cnt[w] = cnt;
        }
        __syncthreads();
        totc = 0;
        bool over = false;
#pragma unroll
        for (int i = 0; i < 8; ++i) {
            int ci = s_cnt[i];
            totc += ci;
            over |= (ci > KNN_WCAP);
        }
        over |= (totc > KNN_TOT);
        if (totc >= target && !over) { valid = true; break; }
        if (totc < target) T = fminf(T * 4.0f, BIGF * 0.4f);
        else               T = T * 0.35f;
        __syncthreads();
    }

    if (valid) {
        int pre[8];
        {
            int acc = 0;
#pragma unroll
            for (int i = 0; i < 8; ++i) { pre[i] = acc; acc += s_cnt[i]; }
        }
        if (totc <= 288) {
            if (tid < totc) {
                int sg = 0;
#pragma unroll
                for (int i = 1; i < 8; ++i) if (tid >= pre[i]) sg = i;
                unsigned long long mine = s_key[sg][tid - pre[sg]];
                int rk = 0;
#pragma unroll
                for (int w2 = 0; w2 < 8; ++w2) {
                    int c2 = s_cnt[w2];
                    for (int j = 0; j < c2; ++j)
                        rk += (s_key[w2][j] < mine) ? 1 : 0;
                }
                if (rk < target)
                    g_knn[m * K_NB + rk] = g_midx[(unsigned)(mine & 0xffffffffu)];
            }
        } else {
            unsigned long long mine[2];
            int rk[2];
#pragma unroll
            for (int o = 0; o < 2; ++o) {
                int g = tid + o * 288;
                unsigned long long k = ~0ull;
                if (g < totc) {
                    int sg = 0;
#pragma unroll
                    for (int i = 1; i < 8; ++i) if (g >= pre[i]) sg = i;
                    k = s_key[sg][g - pre[sg]];
                }
                mine[o] = k;
                rk[o] = 0;
            }
#pragma unroll
            for (int w2 = 0; w2 < 8; ++w2) {
                int c2 = s_cnt[w2];
                for (int j = 0; j < c2; ++j) {
                    unsigned long long kj = s_key[w2][j];
#pragma unroll
                    for (int o = 0; o < 2; ++o) rk[o] += (kj < mine[o]) ? 1 : 0;
                }
            }
#pragma unroll
            for (int o = 0; o < 2; ++o) {
                if (mine[o] != ~0ull && rk[o] < target)
                    g_knn[m * K_NB + rk[o]] = g_midx[(unsigned)(mine[o] & 0xffffffffu)];
            }
        }
    } else if (w == 0) {
        unsigned long long last = 0ull;
        for (int r = 0; r < K_NB; ++r) {
            unsigned long long best = ~0ull;
            for (int j = lane; j < nM; j += 32) {
                float d2 = BIGF;
                if (j != qi) {
                    float4 c = g_cxyz[j];
                    float dx = c.x - me.x, dy = c.y - me.y, dz = c.z - me.z;
                    d2 = dx * dx + dy * dy + dz * dz;
                }
                unsigned long long p = knn_pack(d2, j);
                if (p >= last && p < best) best = p;
            }
#pragma unroll
            for (int off = 16; off; off >>= 1) {
                unsigned long long o = __shfl_xor_sync(FULLW, best, off);
                if (o < best) best = o;
            }
            if (lane == r) {
                float d = __uint_as_float((unsigned)(best >> 32));
                if (best != ~0ull && d < BIGF * 0.5f)
                    g_knn[m * K_NB + r] = g_midx[(unsigned)best & 0xffffffffu];
            }
            last = best + 1ull;
        }
    }
}

// ---------------- L3: per-atom edge attention, 160 threads ----------------
__global__ void __launch_bounds__(160) attn_kernel(
    const int* __restrict__ seq, const float* __restrict__ xyz,
    const int* __restrict__ num_bonds, const float* __restrict__ grads,
    const float* __restrict__ Wo0, float* __restrict__ out) {
    if (blockIdx.x >= g_nM) return;
    int m = g_midx[blockIdx.x];
    int tid = threadIdx.x;
    int lane = tid & 31;

    __shared__ float s_kv[K_NB][OUTC + 1];
    __shared__ float s_q[64];
    __shared__ float s_rbf[K_NB][RBF_N];
    __shared__ float s_dirv[K_NB][3];
    __shared__ float s_l1j[K_NB][KC][3];
    __shared__ float s_inv[K_NB][KC];
    __shared__ int   s_bond[K_NB];
    __shared__ float s_attn[HEADS][K_NB];
    __shared__ float s_o0[64];
    __shared__ float s_coef[K_NB][4];
    __shared__ int   s_idx[K_NB];
    __shared__ float s_ok[K_NB];

    // ---- phase 0: q load + per-edge geometry ----
    if (tid < 64) {
        s_q[tid] = g_Qv[m * 64 + tid];
    } else if (tid < 64 + K_NB) {
        int e = tid - 64;
        int j = g_knn[m * K_NB + e];
        s_idx[e] = j;
        float rx = xyz[j * 3]     - xyz[m * 3];
        float ry = xyz[j * 3 + 1] - xyz[m * 3 + 1];
        float rz = xyz[j * 3 + 2] - xyz[m * 3 + 2];
        float d2 = rx * rx + ry * ry + rz * rz;
        float dist = sqrtf(d2 + EPSF);
        float inv_d = 1.f / dist;
        float dvx = rx * inv_d, dvy = ry * inv_d, dvz = rz * inv_d;
        s_dirv[e][0] = dvx; s_dirv[e][1] = dvy; s_dirv[e][2] = dvz;
        s_ok[e] = (j != m) ? 1.f : 0.f;
#pragma unroll
        for (int c = 0; c < KC; ++c) {
            float lx = grads[(c * M_ATOMS + j) * 3 + 0];
            float ly = grads[(c * M_ATOMS + j) * 3 + 1];
            float lz = grads[(c * M_ATOMS + j) * 3 + 2];
            s_l1j[e][c][0] = lx; s_l1j[e][c][1] = ly; s_l1j[e][c][2] = lz;
            s_inv[e][c] = lx * dvx + ly * dvy + lz * dvz;
        }
        int ri = m / A_ATOM, ai = m % A_ATOM;
        int rj = j / A_ATOM, aj = j % A_ATOM;
        int b = 0;
        if (rj == ri) b = num_bonds[(seq[ri] * A_ATOM + ai) * A_ATOM + aj];
        s_bond[e] = min(max(b, 0), MAXB);
#pragma unroll
        for (int t = 0; t < RBF_N; ++t) {
            float r = dist - 0.4f * (float)t;
            s_rbf[e][t] = __expf(-2.f * r * r);
        }
    }
    __syncthreads();

    // ---- phase 1: kv[e][d] = P[j][d] + b2 + rbf@W2 + W2[16+bond] + inv@Winv ----
    if (tid < OUTC) {
        int d = tid;
        float w2r[RBF_N];
#pragma unroll
        for (int t = 0; t < RBF_N; ++t) w2r[t] = g_W2[t * OUTC + d];
        float wb0 = g_W2[16 * OUTC + d];
        float wb1 = g_W2[17 * OUTC + d];
        float wb2 = g_W2[18 * OUTC + d];
        float wb3 = g_W2[19 * OUTC + d];
        float wb4 = g_W2[20 * OUTC + d];
        float wi0 = g_WT[96 * OUTC + d];
        float wi1 = g_WT[97 * OUTC + d];
        float wi2 = g_WT[98 * OUTC + d];
        float b2  = g_b2[d];
#pragma unroll 8
        for (int e = 0; e < K_NB; ++e) {
            int j = s_idx[e];
            float acc = b2 + g_P[j * OUTC + d];
#pragma unroll
            for (int t = 0; t < RBF_N; ++t)
                acc = fmaf(s_rbf[e][t], w2r[t], acc);
            int b = s_bond[e];
            float wb = wb0;
            if (b == 1) wb = wb1;
            else if (b == 2) wb = wb2;
            else if (b == 3) wb = wb3;
            else if (b == 4) wb = wb4;
            acc += wb;
            acc = fmaf(s_inv[e][0], wi0, acc);
            acc = fmaf(s_inv[e][1], wi1, acc);
            acc = fmaf(s_inv[e][2], wi2, acc);
            s_kv[e][d] = acc;
        }
    }
    __syncthreads();

    // ---- phase 2: logits + softmax fused ----
    {
        int h = tid >> 5;
        if (h < HEADS) {
            float logit = -1e30f;
            if (lane < K_NB) {
                float acc = 0.f;
#pragma unroll
                for (int dh = 0; dh < DHD; ++dh)
                    acc = fmaf(s_q[h * DHD + dh], s_kv[lane][h * DHD + dh], acc);
                logit = (s_ok[lane] > 0.f) ? acc * 0.25f : -1e9f;
            }
            float mx = logit;
#pragma unroll
            for (int off = 16; off > 0; off >>= 1)
                mx = fmaxf(mx, __shfl_xor_sync(FULLW, mx, off));
            float ex = (lane < K_NB) ? __expf(logit - mx) : 0.f;
            float sm = ex;
#pragma unroll
            for (int off = 16; off > 0; off >>= 1)
                sm += __shfl_xor_sync(FULLW, sm, off);
            if (lane < K_NB) s_attn[h][lane] = ex / sm;
        }
    }
    __syncthreads();

    // ---- phase 3: o0, coef ----
    if (tid < 64) {
        int h = tid >> 4;
        float acc = 0.f;
#pragma unroll
        for (int e = 0; e < K_NB; ++e)
            acc = fmaf(s_attn[h][e], s_kv[e][64 + tid], acc);
        s_o0[tid] = acc;
    } else if (tid < 160) {
        int t = tid - 64;
        int e = t % K_NB, c = t / K_NB;
        float acc = 0.f;
#pragma unroll
        for (int h = 0; h < HEADS; ++h)
            acc = fmaf(s_attn[h][e], s_kv[e][128 + h * 4 + c], acc);
        s_coef[e][c] = acc;
    }
    __syncthreads();

    // ---- phase 4: out0 + out1 (warp 2 shuffle reduction) ----
    if (tid < 64) {
        float acc = g_S[m * 64 + tid];
#pragma unroll 8
        for (int i = 0; i < 64; ++i)
            acc = fmaf(s_o0[i], Wo0[i * 64 + tid], acc);
        out[M_ATOMS * 3 + m * 64 + tid] = acc;
    } else if (tid < 96) {
        int e = tid - 64;
        float v0 = 0.f, v1 = 0.f, v2 = 0.f;
        if (e < K_NB) {
            float c0 = s_coef[e][0];
            v0 = c0 * s_dirv[e][0];
            v1 = c0 * s_dirv[e][1];
            v2 = c0 * s_dirv[e][2];
#pragma unroll
            for (int c = 0; c < KC; ++c) {
                float cc = s_coef[e][c + 1];
                v0 = fmaf(cc, s_l1j[e][c][0], v0);
                v1 = fmaf(cc, s_l1j[e][c][1], v1);
                v2 = fmaf(cc, s_l1j[e][c][2], v2);
            }
        }
#pragma unroll
        for (int off = 16; off > 0; off >>= 1) {
            v0 += __shfl_xor_sync(FULLW, v0, off);
            v1 += __shfl_xor_sync(FULLW, v1, off);
            v2 += __shfl_xor_sync(FULLW, v2, off);
        }
        if (e == 0) {
            out[m * 3 + 0] = xyz[m * 3 + 0] + v0 * 0.01f;
            out[m * 3 + 1] = xyz[m * 3 + 1] + v1 * 0.01f;
            out[m * 3 + 2] = xyz[m * 3 + 2] + v2 * 0.01f;
        }
    }
}

// ---------------- launch ----------------
extern "C" void kernel_launch(void* const* d_in, const int* in_sizes, int n_in,
                              void* d_out, int out_size) {
    const int*   seq       = (const int*)d_in[0];
    const float* xyz       = (const float*)d_in[1];
    const void*  aamask    = d_in[2];
    const int*   num_bonds = (const int*)d_in[3];
    const float* state     = (const float*)d_in[4];
    const float* grads     = (const float*)d_in[5];
    int w = 6;
    if (n_in >= 16 && in_sizes[6] == 1) w = 7;
    const float* We    = (const float*)d_in[w + 0];
    const float* be    = (const float*)d_in[w + 1];
    const float* Wq    = (const float*)d_in[w + 2];
    const float* Wk    = (const float*)d_in[w + 3];
    const float* Wv0   = (const float*)d_in[w + 4];
    const float* Wv1   = (const float*)d_in[w + 5];
    const float* Wo0   = (const float*)d_in[w + 6];
    const float* Wself = (const float*)d_in[w + 7];
    const float* b0    = (const float*)d_in[w + 8];
    float* out = (float*)d_out;

    mask_prep_kernel<<<CBLK + PREP_BLK, 256>>>(seq, aamask, Wk, Wv0, Wv1, We, be);
    scatter_kernel<<<CBLK, 256>>>(xyz);
    knnpq_kernel<<<M_ATOMS + PQ_BLOCKS, 288>>>(state, grads, Wq, Wself, b0, xyz, out);
    attn_kernel<<<M_ATOMS, 160>>>(seq, xyz, num_bonds, grads, Wo0, out);
}